// round 3
// baseline (speedup 1.0000x reference)
#include <cuda_runtime.h>
#include <cstdint>

#define L_NUM 63
#define HID_N 8

// compact block count: S(l) = number of (layer,dpair) 64B blocks before layer l
__host__ __device__ __forceinline__ constexpr int S_blk(int l) {
    int m = l >> 1;
    return (l & 1) ? (m + 1) * (m + 1) : m * (m + 1);
}
#define NBLK 1024            // S_blk(63)
#define WT_FLOATS (NBLK*16)  // 16384 floats = 64KB, stays L1-resident

__device__ float  g_Wt[WT_FLOATS];
__device__ float2 g_W2p[L_NUM * HID_N];

// masked / transposed / d-pair-interleaved compact weight table
__global__ void prep_kernel(const float* __restrict__ W1, const float* __restrict__ W2) {
    int i = blockIdx.x * blockDim.x + threadIdx.x;
    if (i < 63 * 32 * 16) {
        int p  = i & 1;
        int h  = (i >> 1) & 7;
        int dp = (i >> 4) & 31;
        int l  = i >> 9;
        if (dp <= (l >> 1)) {
            int d = 2 * dp + p;
            float v = (d <= l) ? W1[l * (HID_N * L_NUM) + h * L_NUM + d] : 0.0f;
            g_Wt[(S_blk(l) + dp) * 16 + h * 2 + p] = v;
        }
    } else {
        int j = i - 63 * 32 * 16;
        if (j < L_NUM * HID_N) {
            int l = j >> 3, h = j & 7;
            g_W2p[j] = make_float2(W2[l * 16 + h], W2[l * 16 + 8 + h]);
        }
    }
}

__device__ __forceinline__ unsigned long long fma2(unsigned long long a,
                                                   unsigned long long b,
                                                   unsigned long long c) {
    unsigned long long d;
    asm("fma.rn.f32x2 %0, %1, %2, %3;" : "=l"(d) : "l"(a), "l"(b), "l"(c));
    return d;
}
__device__ __forceinline__ void unpack2(unsigned long long v, float& lo, float& hi) {
    asm("mov.b64 {%0, %1}, %2;" : "=f"(lo), "=f"(hi) : "l"(v));
}
__device__ __forceinline__ unsigned long long dup2(float f) {
    unsigned long long v;
    asm("mov.b64 %0, {%1, %1};" : "=l"(v) : "f"(f));
    return v;
}
__device__ __forceinline__ float tanh_fast(float a) {
    float y; asm("tanh.approx.f32 %0, %1;" : "=f"(y) : "f"(a)); return y;
}
__device__ __forceinline__ float exp_fast(float a) {
    float y; asm("ex2.approx.f32 %0, %1;" : "=f"(y) : "f"(a * 1.442695041f)); return y;
}

// SMEM float offsets (no weight table in smem anymore)
#define OFF_B1  0
#define OFF_W2P 504             // float2[504] (8B aligned: 504*4 = 2016)
#define OFF_B2  1512
#define OFF_XZ  1640            // 512 rows x 66 floats (row stride 264B, 8B aligned)
#define XZ_STRIDE 66
#define SMEM_FLOATS (1640 + 512*66)

__global__ __launch_bounds__(256, 1)
void flow_kernel(const float* __restrict__ x,
                 const float* __restrict__ ipar,
                 const float* __restrict__ b1g,
                 const float* __restrict__ b2g,
                 float* __restrict__ z_out,
                 float* __restrict__ ld_out,
                 int has_ld)
{
    extern __shared__ float smem[];
    const int tid = threadIdx.x;
    const int base = blockIdx.x * 512;

    // ---- small epilogue tables to smem ----
    {
        for (int i = tid; i < 504; i += 256) smem[OFF_B1 + i] = b1g[i];
        float2* w2d = (float2*)(smem + OFF_W2P);
        for (int i = tid; i < 504; i += 256) w2d[i] = g_W2p[i];
        for (int i = tid; i < 126; i += 256) smem[OFF_B2 + i] = b2g[i];
    }
    // ---- stage x: coalesced global -> padded smem rows ----
    {
        const float2* xg = (const float2*)(x + (size_t)base * 64);
        #pragma unroll
        for (int k = 0; k < 64; k++) {
            int idx = tid + k * 256;            // 0..16383 (512 rows * 32 float2)
            int row = idx >> 5, c2 = idx & 31;
            float2 v = xg[(size_t)row * 32 + c2];
            *(float2*)&smem[OFF_XZ + row * XZ_STRIDE + 2 * c2] = v;
        }
    }
    __syncthreads();

    // ---- pull own two x rows into registers (64 u64 pairs) ----
    const int rowA = tid, rowB = tid + 256;
    unsigned long long xpA[32], xpB[32];
    #pragma unroll
    for (int i = 0; i < 32; i++) {
        xpA[i] = *(const unsigned long long*)&smem[OFF_XZ + rowA * XZ_STRIDE + 2 * i];
        xpB[i] = *(const unsigned long long*)&smem[OFF_XZ + rowB * XZ_STRIDE + 2 * i];
    }

    const float mu0 = ipar[0];
    const float al0 = ipar[1];
    const float e0  = exp_fast(al0);
    float ldA = al0, ldB = al0;
    {
        float a0, a1, b0, b1v;
        unpack2(xpA[0], a0, a1); unpack2(xpB[0], b0, b1v);
        smem[OFF_XZ + rowA * XZ_STRIDE + 0] = a0 * e0 + mu0;
        smem[OFF_XZ + rowB * XZ_STRIDE + 0] = b0 * e0 + mu0;
    }

    // weights read from global (L1-resident 64KB table, warp-uniform broadcast LDG.128)
    const ulonglong2* __restrict__ wg = (const ulonglong2*)g_Wt;

    #pragma unroll
    for (int l = 0; l < L_NUM; l++) {
        unsigned long long accA[8], accB[8];
        #pragma unroll
        for (int j = 0; j < 8; j++) { accA[j] = 0ull; accB[j] = 0ull; }

        const int ndp = (l >> 1) + 1;
        const ulonglong2* wb = wg + S_blk(l) * 4;   // 4 x 16B per (l,dp) block
        #pragma unroll
        for (int dp = 0; dp < ndp; dp++) {
            ulonglong2 w01 = __ldg(&wb[dp * 4 + 0]);
            ulonglong2 w23 = __ldg(&wb[dp * 4 + 1]);
            ulonglong2 w45 = __ldg(&wb[dp * 4 + 2]);
            ulonglong2 w67 = __ldg(&wb[dp * 4 + 3]);
            unsigned long long xa = xpA[dp], xb = xpB[dp];
            accA[0] = fma2(xa, w01.x, accA[0]);  accB[0] = fma2(xb, w01.x, accB[0]);
            accA[1] = fma2(xa, w01.y, accA[1]);  accB[1] = fma2(xb, w01.y, accB[1]);
            accA[2] = fma2(xa, w23.x, accA[2]);  accB[2] = fma2(xb, w23.x, accB[2]);
            accA[3] = fma2(xa, w23.y, accA[3]);  accB[3] = fma2(xb, w23.y, accB[3]);
            accA[4] = fma2(xa, w45.x, accA[4]);  accB[4] = fma2(xb, w45.x, accB[4]);
            accA[5] = fma2(xa, w45.y, accA[5]);  accB[5] = fma2(xb, w45.y, accB[5]);
            accA[6] = fma2(xa, w67.x, accA[6]);  accB[6] = fma2(xb, w67.x, accB[6]);
            accA[7] = fma2(xa, w67.y, accA[7]);  accB[7] = fma2(xb, w67.y, accB[7]);
        }

        // reduce + bias + tanh; layer-2 as packed (mu, alpha) f32x2
        const float* bb = smem + OFF_B1 + l * 8;
        const unsigned long long* w2p = (const unsigned long long*)(smem + OFF_W2P) + l * 8;
        unsigned long long maA, maB;
        {
            float m0 = smem[OFF_B2 + 2 * l], a0 = smem[OFF_B2 + 2 * l + 1];
            unsigned long long init;
            asm("mov.b64 %0, {%1, %2};" : "=l"(init) : "f"(m0), "f"(a0));
            maA = init; maB = init;
        }
        #pragma unroll
        for (int j = 0; j < 8; j++) {
            float loA, hiA, loB, hiB;
            unpack2(accA[j], loA, hiA);
            unpack2(accB[j], loB, hiB);
            float hA = tanh_fast(loA + hiA + bb[j]);
            float hB = tanh_fast(loB + hiB + bb[j]);
            unsigned long long w2 = w2p[j];
            maA = fma2(dup2(hA), w2, maA);
            maB = fma2(dup2(hB), w2, maB);
        }
        float muA, alA, muB, alB;
        unpack2(maA, muA, alA);
        unpack2(maB, muB, alB);
        ldA += alA; ldB += alB;

        float xnA, xnB;
        {
            float lo, hi;
            unpack2(xpA[(l + 1) >> 1], lo, hi); xnA = ((l + 1) & 1) ? hi : lo;
            unpack2(xpB[(l + 1) >> 1], lo, hi); xnB = ((l + 1) & 1) ? hi : lo;
        }
        smem[OFF_XZ + rowA * XZ_STRIDE + l + 1] = xnA * exp_fast(alA) + muA;
        smem[OFF_XZ + rowB * XZ_STRIDE + l + 1] = xnB * exp_fast(alB) + muB;
    }

    if (has_ld) {
        ld_out[base + tid]       = ldA;
        ld_out[base + 256 + tid] = ldB;
    }

    __syncthreads();
    // ---- coalesced z writeback: smem rows -> global ----
    {
        float2* zg = (float2*)(z_out + (size_t)base * 64);
        #pragma unroll
        for (int k = 0; k < 64; k++) {
            int idx = tid + k * 256;
            int row = idx >> 5, c2 = idx & 31;
            float2 v = *(const float2*)&smem[OFF_XZ + row * XZ_STRIDE + 2 * c2];
            zg[(size_t)row * 32 + c2] = v;
        }
    }
}

extern "C" void kernel_launch(void* const* d_in, const int* in_sizes, int n_in,
                              void* d_out, int out_size) {
    const float* x  = (const float*)d_in[0];
    const float* ip = (const float*)d_in[1];
    const float* W1 = (const float*)d_in[2];
    const float* b1 = (const float*)d_in[3];
    const float* W2 = (const float*)d_in[4];
    const float* b2 = (const float*)d_in[5];

    int B = in_sizes[0] / 64;
    float* z   = (float*)d_out;
    float* ldp = z + (size_t)B * 64;
    int has_ld = (out_size >= B * 64 + B) ? 1 : 0;

    size_t smem = (size_t)SMEM_FLOATS * sizeof(float);
    cudaFuncSetAttribute(flow_kernel, cudaFuncAttributeMaxDynamicSharedMemorySize, (int)smem);

    int prep_n = 63 * 32 * 16 + L_NUM * HID_N;
    prep_kernel<<<(prep_n + 255) / 256, 256>>>(W1, W2);
    flow_kernel<<<B / 512, 256, smem>>>(x, ip, b1, b2, z, ldp, has_ld);
}

// round 4
// speedup vs baseline: 1.6101x; 1.6101x over previous
#include <cuda_runtime.h>
#include <cstdint>

#define L_NUM 63
#define HID_N 8

// compact block count: S(l) = number of (layer,dpair) 64B blocks before layer l
__host__ __device__ __forceinline__ constexpr int S_blk(int l) {
    int m = l >> 1;
    return (l & 1) ? (m + 1) * (m + 1) : m * (m + 1);
}
#define NBLK 1024            // S_blk(63)
#define WT_FLOATS (NBLK*16)  // 16384 floats = 64KB in smem

__device__ float  g_Wt[WT_FLOATS];
__device__ float2 g_W2p[L_NUM * HID_N];

// masked / transposed / d-pair-interleaved compact weight table
__global__ void prep_kernel(const float* __restrict__ W1, const float* __restrict__ W2) {
    int i = blockIdx.x * blockDim.x + threadIdx.x;
    if (i < 63 * 32 * 16) {
        int p  = i & 1;
        int h  = (i >> 1) & 7;
        int dp = (i >> 4) & 31;
        int l  = i >> 9;
        if (dp <= (l >> 1)) {
            int d = 2 * dp + p;
            float v = (d <= l) ? W1[l * (HID_N * L_NUM) + h * L_NUM + d] : 0.0f;
            g_Wt[(S_blk(l) + dp) * 16 + h * 2 + p] = v;
        }
    } else {
        int j = i - 63 * 32 * 16;
        if (j < L_NUM * HID_N) {
            int l = j >> 3, h = j & 7;
            g_W2p[j] = make_float2(W2[l * 16 + h], W2[l * 16 + 8 + h]);
        }
    }
}

__device__ __forceinline__ unsigned long long fma2(unsigned long long a,
                                                   unsigned long long b,
                                                   unsigned long long c) {
    unsigned long long d;
    asm("fma.rn.f32x2 %0, %1, %2, %3;" : "=l"(d) : "l"(a), "l"(b), "l"(c));
    return d;
}
__device__ __forceinline__ void unpack2(unsigned long long v, float& lo, float& hi) {
    asm("mov.b64 {%0, %1}, %2;" : "=f"(lo), "=f"(hi) : "l"(v));
}
__device__ __forceinline__ unsigned long long dup2(float f) {
    unsigned long long v;
    asm("mov.b64 %0, {%1, %1};" : "=l"(v) : "f"(f));
    return v;
}
__device__ __forceinline__ float tanh_fast(float a) {
    float y; asm("tanh.approx.f32 %0, %1;" : "=f"(y) : "f"(a)); return y;
}
__device__ __forceinline__ float exp_fast(float a) {
    float y; asm("ex2.approx.f32 %0, %1;" : "=f"(y) : "f"(a * 1.442695041f)); return y;
}

// SMEM float offsets
#define OFF_B1  16384
#define OFF_W2P 16888           // float2[504]
#define OFF_B2  17896
#define OFF_XZ  18024           // 512 rows x 66 floats (row stride 264B, 8B aligned)
#define XZ_STRIDE 66
#define SMEM_FLOATS (18024 + 512*66)

__global__ __launch_bounds__(512, 1)
void flow_kernel(const float* __restrict__ x,
                 const float* __restrict__ ipar,
                 const float* __restrict__ b1g,
                 const float* __restrict__ b2g,
                 float* __restrict__ z_out,
                 float* __restrict__ ld_out,
                 int has_ld)
{
    extern __shared__ float smem[];
    const int tid = threadIdx.x;
    const int base = blockIdx.x * 512;

    // ---- cooperative SMEM fill: weights + epilogue tables ----
    {
        const float4* src = (const float4*)g_Wt;
        float4* dst = (float4*)smem;
        #pragma unroll
        for (int k = 0; k < 8; k++) dst[tid + k * 512] = src[tid + k * 512];
        if (tid < 504) smem[OFF_B1 + tid] = b1g[tid];
        if (tid < 504) ((float2*)(smem + OFF_W2P))[tid] = g_W2p[tid];
        if (tid < 126) smem[OFF_B2 + tid] = b2g[tid];
    }
    // ---- stage x: coalesced global -> padded smem rows ----
    {
        const float2* xg = (const float2*)(x + (size_t)base * 64);
        #pragma unroll
        for (int k = 0; k < 32; k++) {
            int idx = tid + k * 512;            // 0..16383 (512 rows * 32 float2)
            int row = idx >> 5, c2 = idx & 31;
            float2 v = xg[(size_t)row * 32 + c2];
            *(float2*)&smem[OFF_XZ + row * XZ_STRIDE + 2 * c2] = v;
        }
    }
    __syncthreads();

    // ---- pull own x row into registers (32 u64 pairs) ----
    unsigned long long xp[32];
    #pragma unroll
    for (int i = 0; i < 32; i++)
        xp[i] = *(const unsigned long long*)&smem[OFF_XZ + tid * XZ_STRIDE + 2 * i];

    const float mu0 = ipar[0];
    const float al0 = ipar[1];
    float ld = al0;
    {
        float a0, a1; unpack2(xp[0], a0, a1);
        smem[OFF_XZ + tid * XZ_STRIDE + 0] = a0 * exp_fast(al0) + mu0;
    }

    #pragma unroll
    for (int l = 0; l < L_NUM; l++) {
        unsigned long long acc[8];
        #pragma unroll
        for (int j = 0; j < 8; j++) acc[j] = 0ull;

        const int ndp = (l >> 1) + 1;
        const ulonglong2* wb = (const ulonglong2*)(smem + S_blk(l) * 16);
        #pragma unroll
        for (int dp = 0; dp < ndp; dp++) {
            ulonglong2 w01 = wb[dp * 4 + 0];
            ulonglong2 w23 = wb[dp * 4 + 1];
            ulonglong2 w45 = wb[dp * 4 + 2];
            ulonglong2 w67 = wb[dp * 4 + 3];
            unsigned long long xv = xp[dp];
            acc[0] = fma2(xv, w01.x, acc[0]);
            acc[1] = fma2(xv, w01.y, acc[1]);
            acc[2] = fma2(xv, w23.x, acc[2]);
            acc[3] = fma2(xv, w23.y, acc[3]);
            acc[4] = fma2(xv, w45.x, acc[4]);
            acc[5] = fma2(xv, w45.y, acc[5]);
            acc[6] = fma2(xv, w67.x, acc[6]);
            acc[7] = fma2(xv, w67.y, acc[7]);
        }

        // reduce + bias + tanh; layer-2 as packed (mu, alpha) f32x2
        const float* bb = smem + OFF_B1 + l * 8;
        const unsigned long long* w2p = (const unsigned long long*)(smem + OFF_W2P) + l * 8;
        unsigned long long ma;
        {
            float m0 = smem[OFF_B2 + 2 * l], a0 = smem[OFF_B2 + 2 * l + 1];
            asm("mov.b64 %0, {%1, %2};" : "=l"(ma) : "f"(m0), "f"(a0));
        }
        #pragma unroll
        for (int j = 0; j < 8; j++) {
            float lo, hi;
            unpack2(acc[j], lo, hi);
            float h = tanh_fast(lo + hi + bb[j]);
            ma = fma2(dup2(h), w2p[j], ma);
        }
        float mu, al;
        unpack2(ma, mu, al);
        ld += al;

        float xn;
        {
            float lo, hi;
            unpack2(xp[(l + 1) >> 1], lo, hi);
            xn = ((l + 1) & 1) ? hi : lo;
        }
        smem[OFF_XZ + tid * XZ_STRIDE + l + 1] = xn * exp_fast(al) + mu;
    }

    if (has_ld) ld_out[base + tid] = ld;

    __syncthreads();
    // ---- coalesced z writeback: smem rows -> global ----
    {
        float2* zg = (float2*)(z_out + (size_t)base * 64);
        #pragma unroll
        for (int k = 0; k < 32; k++) {
            int idx = tid + k * 512;
            int row = idx >> 5, c2 = idx & 31;
            float2 v = *(const float2*)&smem[OFF_XZ + row * XZ_STRIDE + 2 * c2];
            zg[(size_t)row * 32 + c2] = v;
        }
    }
}

extern "C" void kernel_launch(void* const* d_in, const int* in_sizes, int n_in,
                              void* d_out, int out_size) {
    const float* x  = (const float*)d_in[0];
    const float* ip = (const float*)d_in[1];
    const float* W1 = (const float*)d_in[2];
    const float* b1 = (const float*)d_in[3];
    const float* W2 = (const float*)d_in[4];
    const float* b2 = (const float*)d_in[5];

    int B = in_sizes[0] / 64;
    float* z   = (float*)d_out;
    float* ldp = z + (size_t)B * 64;
    int has_ld = (out_size >= B * 64 + B) ? 1 : 0;

    size_t smem = (size_t)SMEM_FLOATS * sizeof(float);
    cudaFuncSetAttribute(flow_kernel, cudaFuncAttributeMaxDynamicSharedMemorySize, (int)smem);

    int prep_n = 63 * 32 * 16 + L_NUM * HID_N;
    prep_kernel<<<(prep_n + 255) / 256, 256>>>(W1, W2);
    flow_kernel<<<B / 512, 512, smem>>>(x, ip, b1, b2, z, ldp, has_ld);
}